// round 1
// baseline (speedup 1.0000x reference)
#include <cuda_runtime.h>
#include <cuda_bf16.h>
#include <math.h>

#define S_TOT 8196
#define L_PAT 8192
#define H_NUM 8
#define HD 64
#define NUM_CLS 4
#define WIN 32
#define WLEN 65
#define CTX 69

// scratch: qkv in [sel][h][s][hd] layout, attn in [s][h*64+d]
__device__ float g_qkv[3ull * H_NUM * S_TOT * HD];   // ~50 MB
__device__ float g_attn[(size_t)S_TOT * 512];        // ~16.8 MB

// ---------------------------------------------------------------------------
// SGEMM: C[M,N] = A[M,K] * B[N,K]^T + bias[N]
// MODE 0: plain write to C.  MODE 1: scatter into g_qkv (M must be S_TOT).
// BM=BN=128, BK=8, 256 threads, 8x8 microtile.
// ---------------------------------------------------------------------------
template<int MODE>
__launch_bounds__(256)
__global__ void sgemm(const float* __restrict__ A, const float* __restrict__ Bm,
                      const float* __restrict__ bias, float* __restrict__ C,
                      int M, int N, int K) {
    __shared__ float As[8][128];
    __shared__ float Bs[8][128];
    const int tid = threadIdx.x;
    const int bm = blockIdx.y * 128;
    const int bn = blockIdx.x * 128;
    const int tm = (tid >> 4) * 8;
    const int tn = (tid & 15) * 8;
    const int lr = tid >> 1;
    const int lc = (tid & 1) * 4;

    float acc[8][8];
#pragma unroll
    for (int i = 0; i < 8; i++)
#pragma unroll
        for (int j = 0; j < 8; j++) acc[i][j] = 0.f;

    for (int k0 = 0; k0 < K; k0 += 8) {
        // load A tile (transposed)
        {
            int row = bm + lr;
            float4 a = make_float4(0.f, 0.f, 0.f, 0.f);
            if (row < M) a = *reinterpret_cast<const float4*>(&A[(size_t)row * K + k0 + lc]);
            As[lc + 0][lr] = a.x; As[lc + 1][lr] = a.y;
            As[lc + 2][lr] = a.z; As[lc + 3][lr] = a.w;
            int col = bn + lr;
            float4 b = make_float4(0.f, 0.f, 0.f, 0.f);
            if (col < N) b = *reinterpret_cast<const float4*>(&Bm[(size_t)col * K + k0 + lc]);
            Bs[lc + 0][lr] = b.x; Bs[lc + 1][lr] = b.y;
            Bs[lc + 2][lr] = b.z; Bs[lc + 3][lr] = b.w;
        }
        __syncthreads();
#pragma unroll
        for (int kk = 0; kk < 8; kk++) {
            float a[8], b[8];
            *(float4*)&a[0] = *(float4*)&As[kk][tm];
            *(float4*)&a[4] = *(float4*)&As[kk][tm + 4];
            *(float4*)&b[0] = *(float4*)&Bs[kk][tn];
            *(float4*)&b[4] = *(float4*)&Bs[kk][tn + 4];
#pragma unroll
            for (int i = 0; i < 8; i++)
#pragma unroll
                for (int j = 0; j < 8; j++) acc[i][j] = fmaf(a[i], b[j], acc[i][j]);
        }
        __syncthreads();
    }

    // epilogue
    const int n0 = bn + tn;
    float bv[8];
#pragma unroll
    for (int j = 0; j < 8; j++) bv[j] = bias[n0 + j];

#pragma unroll
    for (int i = 0; i < 8; i++) {
        int m = bm + tm + i;
        if (m >= M) continue;
        float v[8];
#pragma unroll
        for (int j = 0; j < 8; j++) v[j] = acc[i][j] + bv[j];
        if (MODE == 0) {
            float* dst = &C[(size_t)m * N + n0];
            *(float4*)&dst[0] = *(float4*)&v[0];
            *(float4*)&dst[4] = *(float4*)&v[4];
        } else {
            // n0..n0+7 stay within one (sel, h, d-block) since n0 % 8 == 0
            int sel = n0 >> 9;
            int h = (n0 >> 6) & 7;
            int d = n0 & 63;
            float* dst = &g_qkv[(((size_t)(sel * 8 + h) * S_TOT) + m) * 64 + d];
            *(float4*)&dst[0] = *(float4*)&v[0];
            *(float4*)&dst[4] = *(float4*)&v[4];
        }
    }
}

// ---------------------------------------------------------------------------
// RoPE2D in-place on q_p and k_p (rows NUM_CLS..S-1)
// block = token l (0..8191), 256 threads: h = tid/32, pair p = tid%32
// ---------------------------------------------------------------------------
__global__ void rope_kernel(const float* __restrict__ coords) {
    int l = blockIdx.x;
    int tid = threadIdx.x;
    int h = tid >> 5;
    int p = tid & 31;
    float cx = coords[2 * l + 0];
    float cy = coords[2 * l + 1];
    int j = p & 15;
    // inv_freq = 10000^{-(2j)/32} = exp(-j/16 * ln(10000))
    float freq = __expf(-(float)j * (9.210340371976184f / 16.0f));
    float coord = ((p < 16) ? cx : cy) * 1e-5f;
    float ang = coord * freq;
    float s, c;
    __sincosf(ang, &s, &c);

    size_t base_q = (((size_t)(0 * 8 + h) * S_TOT) + NUM_CLS + l) * 64 + 2 * p;
    size_t base_k = (((size_t)(1 * 8 + h) * S_TOT) + NUM_CLS + l) * 64 + 2 * p;
    float2 q = *(float2*)&g_qkv[base_q];
    *(float2*)&g_qkv[base_q] = make_float2(q.x * c - q.y * s, q.y * c + q.x * s);
    float2 k = *(float2*)&g_qkv[base_k];
    *(float2*)&g_qkv[base_k] = make_float2(k.x * c - k.y * s, k.y * c + k.x * s);
}

// ---------------------------------------------------------------------------
// CLS attention: 32 blocks (h = b/4, ci = b%4), 256 threads.
// Full softmax over all S_TOT keys, output row ci of attn.
// ---------------------------------------------------------------------------
__launch_bounds__(256)
__global__ void cls_attn_kernel() {
    __shared__ float qs[64];
    __shared__ float sc[S_TOT];
    __shared__ float red[32];
    __shared__ float osum[8][64];

    int h = blockIdx.x >> 2;
    int ci = blockIdx.x & 3;
    int tid = threadIdx.x;
    int lane = tid & 31, w = tid >> 5;

    const float* Q = &g_qkv[(((size_t)(0 * 8 + h) * S_TOT) + ci) * 64];
    const float* Kb = &g_qkv[(size_t)(1 * 8 + h) * S_TOT * 64];
    const float* Vb = &g_qkv[(size_t)(2 * 8 + h) * S_TOT * 64];

    if (tid < 64) qs[tid] = Q[tid];
    __syncthreads();

    float lmax = -INFINITY;
    for (int s = tid; s < S_TOT; s += 256) {
        const float4* kr = (const float4*)(Kb + (size_t)s * 64);
        float a = 0.f;
#pragma unroll
        for (int i = 0; i < 16; i++) {
            float4 kv = kr[i];
            float4 qv = *(float4*)&qs[i * 4];
            a += kv.x * qv.x + kv.y * qv.y + kv.z * qv.z + kv.w * qv.w;
        }
        a *= 0.125f;
        sc[s] = a;
        lmax = fmaxf(lmax, a);
    }
#pragma unroll
    for (int o = 16; o > 0; o >>= 1) lmax = fmaxf(lmax, __shfl_xor_sync(0xffffffffu, lmax, o));
    if (lane == 0) red[w] = lmax;
    __syncthreads();
    float gmax = red[0];
#pragma unroll
    for (int i = 1; i < 8; i++) gmax = fmaxf(gmax, red[i]);
    __syncthreads();

    float lsum = 0.f;
    for (int s = tid; s < S_TOT; s += 256) {
        float p = __expf(sc[s] - gmax);
        sc[s] = p;
        lsum += p;
    }
#pragma unroll
    for (int o = 16; o > 0; o >>= 1) lsum += __shfl_xor_sync(0xffffffffu, lsum, o);
    if (lane == 0) red[w] = lsum;
    __syncthreads();
    float gsum = 0.f;
#pragma unroll
    for (int i = 0; i < 8; i++) gsum += red[i];
    float inv = 1.0f / gsum;

    float acc[64];
#pragma unroll
    for (int d = 0; d < 64; d++) acc[d] = 0.f;
    for (int s = tid; s < S_TOT; s += 256) {
        float p = sc[s] * inv;
        const float4* vr = (const float4*)(Vb + (size_t)s * 64);
#pragma unroll
        for (int i = 0; i < 16; i++) {
            float4 vv = vr[i];
            acc[i * 4 + 0] = fmaf(p, vv.x, acc[i * 4 + 0]);
            acc[i * 4 + 1] = fmaf(p, vv.y, acc[i * 4 + 1]);
            acc[i * 4 + 2] = fmaf(p, vv.z, acc[i * 4 + 2]);
            acc[i * 4 + 3] = fmaf(p, vv.w, acc[i * 4 + 3]);
        }
    }
#pragma unroll
    for (int d = 0; d < 64; d++) {
        float v = acc[d];
#pragma unroll
        for (int o = 16; o > 0; o >>= 1) v += __shfl_down_sync(0xffffffffu, v, o);
        if (lane == 0) osum[w][d] = v;
    }
    __syncthreads();
    if (tid < 64) {
        float v = 0.f;
#pragma unroll
        for (int i = 0; i < 8; i++) v += osum[i][tid];
        g_attn[(size_t)ci * 512 + h * 64 + tid] = v;
    }
}

// ---------------------------------------------------------------------------
// Patch attention: block = (64-token tile, head). 256 threads. dyn smem.
// smem: qs[64*64], ks[128*65], vs[128*64], kc[4*64], vc[4*64], sc[64*72]
// ---------------------------------------------------------------------------
#define PATCH_SMEM ((64*64 + 128*65 + 128*64 + 256 + 256 + 64*72) * 4)

__launch_bounds__(256)
__global__ void patch_attn_kernel() {
    extern __shared__ float sm[];
    float* qs = sm;                 // 64 x 64
    float* ks = qs + 64 * 64;       // 128 x 65 (padded for conflict-free scalar reads)
    float* vs = ks + 128 * 65;      // 128 x 64 (vectorized reads)
    float* kc = vs + 128 * 64;      // 4 x 64
    float* vc = kc + 256;           // 4 x 64
    float* sc = vc + 256;           // 64 x 72

    int h = blockIdx.y;
    int l0 = blockIdx.x * 64;
    int tid = threadIdx.x;

    const float* Qb = &g_qkv[(size_t)(0 * 8 + h) * S_TOT * 64];
    const float* Kb = &g_qkv[(size_t)(1 * 8 + h) * S_TOT * 64];
    const float* Vb = &g_qkv[(size_t)(2 * 8 + h) * S_TOT * 64];

    // q tile
    for (int i = tid; i < 64 * 16; i += 256) {
        int r = i >> 4, c4 = (i & 15) << 2;
        float4 v = *(const float4*)&Qb[(size_t)(NUM_CLS + l0 + r) * 64 + c4];
        *(float4*)&qs[r * 64 + c4] = v;
    }
    // k/v window: rows l0-32 .. l0+95
    for (int i = tid; i < 128 * 16; i += 256) {
        int r = i >> 4, c4 = (i & 15) << 2;
        int kp = l0 - WIN + r;
        float4 kv = make_float4(0.f, 0.f, 0.f, 0.f);
        float4 vv = make_float4(0.f, 0.f, 0.f, 0.f);
        if (kp >= 0 && kp < L_PAT) {
            kv = *(const float4*)&Kb[(size_t)(NUM_CLS + kp) * 64 + c4];
            vv = *(const float4*)&Vb[(size_t)(NUM_CLS + kp) * 64 + c4];
        }
        ks[r * 65 + c4 + 0] = kv.x; ks[r * 65 + c4 + 1] = kv.y;
        ks[r * 65 + c4 + 2] = kv.z; ks[r * 65 + c4 + 3] = kv.w;
        *(float4*)&vs[r * 64 + c4] = vv;
    }
    // cls k/v
    if (tid < 64) {
        int r = tid >> 4, c4 = (tid & 15) << 2;
        *(float4*)&kc[r * 64 + c4] = *(const float4*)&Kb[(size_t)r * 64 + c4];
        *(float4*)&vc[r * 64 + c4] = *(const float4*)&Vb[(size_t)r * 64 + c4];
    }
    __syncthreads();

    // scores: 64 q x 69 keys
    for (int pr = tid; pr < 64 * CTX; pr += 256) {
        int qi = pr / CTX, j = pr % CTX;
        const float* qrow = &qs[qi * 64];
        const float* krow;
        bool valid = true;
        if (j < NUM_CLS) {
            krow = &kc[j * 64];
        } else {
            int wq = j - NUM_CLS;
            int pos = l0 + qi - WIN + wq;
            valid = (pos >= 0) && (pos < L_PAT);
            krow = &ks[(qi + wq) * 65];
        }
        float a = 0.f;
#pragma unroll
        for (int d = 0; d < 64; d++) a = fmaf(qrow[d], krow[d], a);
        sc[qi * 72 + j] = valid ? a * 0.125f : -1e30f;
    }
    __syncthreads();

    // softmax: 4 threads per row
    {
        int row = tid >> 2, sub = tid & 3;
        float* srow = &sc[row * 72];
        float m = -INFINITY;
        for (int j = sub; j < CTX; j += 4) m = fmaxf(m, srow[j]);
        m = fmaxf(m, __shfl_xor_sync(0xffffffffu, m, 1));
        m = fmaxf(m, __shfl_xor_sync(0xffffffffu, m, 2));
        float sum = 0.f;
        for (int j = sub; j < CTX; j += 4) {
            float p = __expf(srow[j] - m);
            srow[j] = p;
            sum += p;
        }
        sum += __shfl_xor_sync(0xffffffffu, sum, 1);
        sum += __shfl_xor_sync(0xffffffffu, sum, 2);
        float inv = 1.0f / sum;
        for (int j = sub; j < CTX; j += 4) srow[j] *= inv;
    }
    __syncthreads();

    // output: 64 q x 64 d, vectorized by 4 over d
    for (int i = tid; i < 64 * 16; i += 256) {
        int qi = i >> 4, d4 = (i & 15) << 2;
        const float* prow = &sc[qi * 72];
        float4 a = make_float4(0.f, 0.f, 0.f, 0.f);
#pragma unroll
        for (int j = 0; j < NUM_CLS; j++) {
            float p = prow[j];
            float4 vv = *(float4*)&vc[j * 64 + d4];
            a.x = fmaf(p, vv.x, a.x); a.y = fmaf(p, vv.y, a.y);
            a.z = fmaf(p, vv.z, a.z); a.w = fmaf(p, vv.w, a.w);
        }
#pragma unroll
        for (int wq = 0; wq < WLEN; wq++) {
            float p = prow[NUM_CLS + wq];
            float4 vv = *(float4*)&vs[(qi + wq) * 64 + d4];
            a.x = fmaf(p, vv.x, a.x); a.y = fmaf(p, vv.y, a.y);
            a.z = fmaf(p, vv.z, a.z); a.w = fmaf(p, vv.w, a.w);
        }
        *(float4*)&g_attn[(size_t)(NUM_CLS + l0 + qi) * 512 + h * 64 + d4] = a;
    }
}

// ---------------------------------------------------------------------------
extern "C" void kernel_launch(void* const* d_in, const int* in_sizes, int n_in,
                              void* d_out, int out_size) {
    const float* x      = (const float*)d_in[0];
    const float* coords = (const float*)d_in[1];
    const float* w_qkv  = (const float*)d_in[2];
    const float* b_qkv  = (const float*)d_in[3];
    const float* w_out  = (const float*)d_in[4];
    const float* b_out  = (const float*)d_in[5];
    float* out = (float*)d_out;

    float* attn_ptr = nullptr;
    cudaGetSymbolAddress((void**)&attn_ptr, g_attn);

    // 1. QKV GEMM: [8196,512] x [1536,512]^T -> scatter to g_qkv
    {
        dim3 grid(1536 / 128, (S_TOT + 127) / 128);
        sgemm<1><<<grid, 256>>>(x, w_qkv, b_qkv, nullptr, S_TOT, 1536, 512);
    }
    // 2. RoPE on q_p, k_p
    rope_kernel<<<L_PAT, 256>>>(coords);
    // 3. CLS attention
    cls_attn_kernel<<<32, 256>>>();
    // 4. Patch attention
    cudaFuncSetAttribute(patch_attn_kernel,
                         cudaFuncAttributeMaxDynamicSharedMemorySize, PATCH_SMEM);
    {
        dim3 grid(L_PAT / 64, H_NUM);
        patch_attn_kernel<<<grid, 256, PATCH_SMEM>>>();
    }
    // 5. Output projection: attn [8196,512] x [512,512]^T + b -> out
    {
        dim3 grid(512 / 128, (S_TOT + 127) / 128);
        sgemm<0><<<grid, 256>>>(attn_ptr, w_out, b_out, out, S_TOT, 512, 512);
    }
}

// round 4
// speedup vs baseline: 1.5908x; 1.5908x over previous
#include <cuda_runtime.h>
#include <cuda_bf16.h>
#include <math.h>
#include <stdint.h>

#define S_TOT 8196
#define L_PAT 8192
#define H_NUM 8
#define HD 64
#define NUM_CLS 4
#define WIN 32
#define WLEN 65
#define CTX 69
#define GK 512

// scratch: qkv in [sel][h][s][hd] layout, attn in [s][h*64+d]
__device__ float g_qkv[3ull * H_NUM * S_TOT * HD];
__device__ float g_attn[(size_t)S_TOT * 512];
// bf16 hi/lo split buffers
__device__ __nv_bfloat16 g_xh[(size_t)S_TOT * GK];
__device__ __nv_bfloat16 g_xl[(size_t)S_TOT * GK];
__device__ __nv_bfloat16 g_wqh[1536 * GK];
__device__ __nv_bfloat16 g_wql[1536 * GK];
__device__ __nv_bfloat16 g_woh[512 * GK];
__device__ __nv_bfloat16 g_wol[512 * GK];
__device__ __nv_bfloat16 g_ah[(size_t)S_TOT * GK];
__device__ __nv_bfloat16 g_al[(size_t)S_TOT * GK];

// single dynamic smem symbol shared by all kernels
extern __shared__ char dynsm[];

__device__ __forceinline__ uint32_t smem_u32(const void* p) {
    uint32_t a;
    asm("{ .reg .u64 t; cvta.to.shared.u64 t, %1; cvt.u32.u64 %0, t; }" : "=r"(a) : "l"(p));
    return a;
}
__device__ __forceinline__ void ldm_x4(uint32_t* r, uint32_t addr) {
    asm volatile("ldmatrix.sync.aligned.m8n8.x4.shared.b16 {%0,%1,%2,%3}, [%4];"
                 : "=r"(r[0]), "=r"(r[1]), "=r"(r[2]), "=r"(r[3]) : "r"(addr));
}
__device__ __forceinline__ void mma16816(float* c, const uint32_t* a, uint32_t b0, uint32_t b1) {
    asm volatile("mma.sync.aligned.m16n8k16.row.col.f32.bf16.bf16.f32 "
                 "{%0,%1,%2,%3}, {%4,%5,%6,%7}, {%8,%9}, {%0,%1,%2,%3};"
                 : "+f"(c[0]), "+f"(c[1]), "+f"(c[2]), "+f"(c[3])
                 : "r"(a[0]), "r"(a[1]), "r"(a[2]), "r"(a[3]), "r"(b0), "r"(b1));
}

// ---------------------------------------------------------------------------
// split: fp32 -> (hi, lo) bf16
// ---------------------------------------------------------------------------
__global__ void split_kernel(const float* __restrict__ src,
                             __nv_bfloat16* __restrict__ hi,
                             __nv_bfloat16* __restrict__ lo, int n4) {
    int i = blockIdx.x * 256 + threadIdx.x;
    if (i >= n4) return;
    float4 v = *(const float4*)(src + (size_t)i * 4);
    __nv_bfloat16 h0 = __float2bfloat16(v.x), h1 = __float2bfloat16(v.y);
    __nv_bfloat16 h2 = __float2bfloat16(v.z), h3 = __float2bfloat16(v.w);
    __nv_bfloat16 l0 = __float2bfloat16(v.x - __bfloat162float(h0));
    __nv_bfloat16 l1 = __float2bfloat16(v.y - __bfloat162float(h1));
    __nv_bfloat16 l2 = __float2bfloat16(v.z - __bfloat162float(h2));
    __nv_bfloat16 l3 = __float2bfloat16(v.w - __bfloat162float(h3));
    __nv_bfloat162* hp = (__nv_bfloat162*)(hi + (size_t)i * 4);
    __nv_bfloat162* lp = (__nv_bfloat162*)(lo + (size_t)i * 4);
    hp[0] = __nv_bfloat162(h0, h1); hp[1] = __nv_bfloat162(h2, h3);
    lp[0] = __nv_bfloat162(l0, l1); lp[1] = __nv_bfloat162(l2, l3);
}

// ---------------------------------------------------------------------------
// bf16x3 mma.sync GEMM: C[M,N] = A[M,GK] * B[N,GK]^T + bias
// CTA tile 128x128, 8 warps (2x4), warp tile 64x32, k-chunks of 64.
// MODE 0: row-major C.  MODE 1: scatter into g_qkv.
// ---------------------------------------------------------------------------
#define SMS 72                       // smem row stride in bf16 (144B)
#define TILE_ELEMS (128 * SMS)       // per operand array
#define GEMM_SMEM (4 * TILE_ELEMS * 2)

template<int MODE>
__launch_bounds__(256)
__global__ void gemm_bf16x3(const __nv_bfloat16* __restrict__ Ah,
                            const __nv_bfloat16* __restrict__ Al,
                            const __nv_bfloat16* __restrict__ Bh,
                            const __nv_bfloat16* __restrict__ Bl,
                            const float* __restrict__ bias,
                            float* __restrict__ C, int M, int Ntot) {
    __nv_bfloat16* sm = (__nv_bfloat16*)dynsm;
    __nv_bfloat16* sAh = sm;
    __nv_bfloat16* sAl = sm + TILE_ELEMS;
    __nv_bfloat16* sBh = sm + 2 * TILE_ELEMS;
    __nv_bfloat16* sBl = sm + 3 * TILE_ELEMS;

    const int tid = threadIdx.x;
    const int wid = tid >> 5;
    const int lane = tid & 31;
    const int wm = (wid >> 2) * 64;      // warp m offset in tile
    const int wn = (wid & 3) * 32;       // warp n offset in tile
    const int bm = blockIdx.y * 128;
    const int bn = blockIdx.x * 128;

    float c[4][4][4];
#pragma unroll
    for (int i = 0; i < 4; i++)
#pragma unroll
        for (int j = 0; j < 4; j++)
#pragma unroll
            for (int r = 0; r < 4; r++) c[i][j][r] = 0.f;

    const uint32_t a_h = smem_u32(sAh), a_l = smem_u32(sAl);
    const uint32_t b_h = smem_u32(sBh), b_l = smem_u32(sBl);
    // ldmatrix lane addressing: row += lane&15, col += (lane>>4)*8
    const int lrow = lane & 15;
    const int lcol = (lane >> 4) * 8;

    for (int ch = 0; ch < GK / 64; ch++) {
        // load 64-k chunk of all four operands
#pragma unroll
        for (int it = 0; it < 4; it++) {
            int i = tid + it * 256;
            int row = i >> 3, q = i & 7;
            int gr = bm + row;
            uint4 vh = make_uint4(0, 0, 0, 0), vl = make_uint4(0, 0, 0, 0);
            if (gr < M) {
                size_t off = (size_t)gr * GK + ch * 64 + q * 8;
                vh = *(const uint4*)(Ah + off);
                vl = *(const uint4*)(Al + off);
            }
            *(uint4*)(sAh + row * SMS + q * 8) = vh;
            *(uint4*)(sAl + row * SMS + q * 8) = vl;
            size_t boff = (size_t)(bn + row) * GK + ch * 64 + q * 8;
            *(uint4*)(sBh + row * SMS + q * 8) = *(const uint4*)(Bh + boff);
            *(uint4*)(sBl + row * SMS + q * 8) = *(const uint4*)(Bl + boff);
        }
        __syncthreads();

#pragma unroll
        for (int kk = 0; kk < 4; kk++) {
            uint32_t afh[4][4], afl[4][4], bfh[2][4], bfl[2][4];
#pragma unroll
            for (int mt = 0; mt < 4; mt++) {
                uint32_t off = ((wm + mt * 16 + lrow) * SMS + kk * 16 + lcol) * 2;
                ldm_x4(afh[mt], a_h + off);
                ldm_x4(afl[mt], a_l + off);
            }
#pragma unroll
            for (int g = 0; g < 2; g++) {
                uint32_t off = ((wn + g * 16 + lrow) * SMS + kk * 16 + lcol) * 2;
                ldm_x4(bfh[g], b_h + off);
                ldm_x4(bfl[g], b_l + off);
            }
#pragma unroll
            for (int mt = 0; mt < 4; mt++) {
#pragma unroll
                for (int nt = 0; nt < 4; nt++) {
                    int g = nt >> 1, s = nt & 1;
                    mma16816(c[mt][nt], afh[mt], bfh[g][s], bfh[g][s + 2]);
                    mma16816(c[mt][nt], afh[mt], bfl[g][s], bfl[g][s + 2]);
                    mma16816(c[mt][nt], afl[mt], bfh[g][s], bfh[g][s + 2]);
                }
            }
        }
        __syncthreads();
    }

    // epilogue: write fragments + bias
    const int gid = lane >> 2;     // 0..7
    const int tig = lane & 3;      // 0..3
#pragma unroll
    for (int mt = 0; mt < 4; mt++) {
#pragma unroll
        for (int nt = 0; nt < 4; nt++) {
            int n = bn + wn + nt * 8 + tig * 2;
            float bx = bias[n], by = bias[n + 1];
            int m0 = bm + wm + mt * 16 + gid;
#pragma unroll
            for (int half = 0; half < 2; half++) {
                int m = m0 + half * 8;
                if (m >= M) continue;
                float vx = c[mt][nt][half * 2 + 0] + bx;
                float vy = c[mt][nt][half * 2 + 1] + by;
                if (MODE == 0) {
                    float2* dst = (float2*)&C[(size_t)m * Ntot + n];
                    *dst = make_float2(vx, vy);
                } else {
                    int sel = n >> 9, h = (n >> 6) & 7, d = n & 63;
                    float2* dst = (float2*)&g_qkv[(((size_t)(sel * 8 + h) * S_TOT) + m) * 64 + d];
                    *dst = make_float2(vx, vy);
                }
            }
        }
    }
}

// ---------------------------------------------------------------------------
// RoPE2D in-place on q_p and k_p
// ---------------------------------------------------------------------------
__global__ void rope_kernel(const float* __restrict__ coords) {
    int l = blockIdx.x;
    int tid = threadIdx.x;
    int h = tid >> 5;
    int p = tid & 31;
    float cx = coords[2 * l + 0];
    float cy = coords[2 * l + 1];
    int j = p & 15;
    float freq = __expf(-(float)j * (9.210340371976184f / 16.0f));
    float coord = ((p < 16) ? cx : cy) * 1e-5f;
    float ang = coord * freq;
    float s, c;
    __sincosf(ang, &s, &c);

    size_t base_q = (((size_t)(0 * 8 + h) * S_TOT) + NUM_CLS + l) * 64 + 2 * p;
    size_t base_k = (((size_t)(1 * 8 + h) * S_TOT) + NUM_CLS + l) * 64 + 2 * p;
    float2 q = *(float2*)&g_qkv[base_q];
    *(float2*)&g_qkv[base_q] = make_float2(q.x * c - q.y * s, q.y * c + q.x * s);
    float2 k = *(float2*)&g_qkv[base_k];
    *(float2*)&g_qkv[base_k] = make_float2(k.x * c - k.y * s, k.y * c + k.x * s);
}

// ---------------------------------------------------------------------------
// CLS attention
// ---------------------------------------------------------------------------
__launch_bounds__(256)
__global__ void cls_attn_kernel() {
    __shared__ float qs[64];
    __shared__ float sc[S_TOT];
    __shared__ float red[32];
    __shared__ float osum[8][64];

    int h = blockIdx.x >> 2;
    int ci = blockIdx.x & 3;
    int tid = threadIdx.x;
    int lane = tid & 31, w = tid >> 5;

    const float* Q = &g_qkv[(((size_t)(0 * 8 + h) * S_TOT) + ci) * 64];
    const float* Kb = &g_qkv[(size_t)(1 * 8 + h) * S_TOT * 64];
    const float* Vb = &g_qkv[(size_t)(2 * 8 + h) * S_TOT * 64];

    if (tid < 64) qs[tid] = Q[tid];
    __syncthreads();

    float lmax = -INFINITY;
    for (int s = tid; s < S_TOT; s += 256) {
        const float4* kr = (const float4*)(Kb + (size_t)s * 64);
        float a = 0.f;
#pragma unroll
        for (int i = 0; i < 16; i++) {
            float4 kv = kr[i];
            float4 qv = *(float4*)&qs[i * 4];
            a += kv.x * qv.x + kv.y * qv.y + kv.z * qv.z + kv.w * qv.w;
        }
        a *= 0.125f;
        sc[s] = a;
        lmax = fmaxf(lmax, a);
    }
#pragma unroll
    for (int o = 16; o > 0; o >>= 1) lmax = fmaxf(lmax, __shfl_xor_sync(0xffffffffu, lmax, o));
    if (lane == 0) red[w] = lmax;
    __syncthreads();
    float gmax = red[0];
#pragma unroll
    for (int i = 1; i < 8; i++) gmax = fmaxf(gmax, red[i]);
    __syncthreads();

    float lsum = 0.f;
    for (int s = tid; s < S_TOT; s += 256) {
        float p = __expf(sc[s] - gmax);
        sc[s] = p;
        lsum += p;
    }
#pragma unroll
    for (int o = 16; o > 0; o >>= 1) lsum += __shfl_xor_sync(0xffffffffu, lsum, o);
    if (lane == 0) red[w] = lsum;
    __syncthreads();
    float gsum = 0.f;
#pragma unroll
    for (int i = 0; i < 8; i++) gsum += red[i];
    float inv = 1.0f / gsum;

    float acc[64];
#pragma unroll
    for (int d = 0; d < 64; d++) acc[d] = 0.f;
    for (int s = tid; s < S_TOT; s += 256) {
        float p = sc[s] * inv;
        const float4* vr = (const float4*)(Vb + (size_t)s * 64);
#pragma unroll
        for (int i = 0; i < 16; i++) {
            float4 vv = vr[i];
            acc[i * 4 + 0] = fmaf(p, vv.x, acc[i * 4 + 0]);
            acc[i * 4 + 1] = fmaf(p, vv.y, acc[i * 4 + 1]);
            acc[i * 4 + 2] = fmaf(p, vv.z, acc[i * 4 + 2]);
            acc[i * 4 + 3] = fmaf(p, vv.w, acc[i * 4 + 3]);
        }
    }
#pragma unroll
    for (int d = 0; d < 64; d++) {
        float v = acc[d];
#pragma unroll
        for (int o = 16; o > 0; o >>= 1) v += __shfl_down_sync(0xffffffffu, v, o);
        if (lane == 0) osum[w][d] = v;
    }
    __syncthreads();
    if (tid < 64) {
        float v = 0.f;
#pragma unroll
        for (int i = 0; i < 8; i++) v += osum[i][tid];
        g_attn[(size_t)ci * 512 + h * 64 + tid] = v;
    }
}

// ---------------------------------------------------------------------------
// Patch attention
// ---------------------------------------------------------------------------
#define PATCH_SMEM ((64*64 + 128*65 + 128*64 + 256 + 256 + 64*72) * 4)

__launch_bounds__(256)
__global__ void patch_attn_kernel() {
    float* sm = (float*)dynsm;
    float* qs = sm;
    float* ks = qs + 64 * 64;
    float* vs = ks + 128 * 65;
    float* kc = vs + 128 * 64;
    float* vc = kc + 256;
    float* sc = vc + 256;

    int h = blockIdx.y;
    int l0 = blockIdx.x * 64;
    int tid = threadIdx.x;

    const float* Qb = &g_qkv[(size_t)(0 * 8 + h) * S_TOT * 64];
    const float* Kb = &g_qkv[(size_t)(1 * 8 + h) * S_TOT * 64];
    const float* Vb = &g_qkv[(size_t)(2 * 8 + h) * S_TOT * 64];

    for (int i = tid; i < 64 * 16; i += 256) {
        int r = i >> 4, c4 = (i & 15) << 2;
        float4 v = *(const float4*)&Qb[(size_t)(NUM_CLS + l0 + r) * 64 + c4];
        *(float4*)&qs[r * 64 + c4] = v;
    }
    for (int i = tid; i < 128 * 16; i += 256) {
        int r = i >> 4, c4 = (i & 15) << 2;
        int kp = l0 - WIN + r;
        float4 kv = make_float4(0.f, 0.f, 0.f, 0.f);
        float4 vv = make_float4(0.f, 0.f, 0.f, 0.f);
        if (kp >= 0 && kp < L_PAT) {
            kv = *(const float4*)&Kb[(size_t)(NUM_CLS + kp) * 64 + c4];
            vv = *(const float4*)&Vb[(size_t)(NUM_CLS + kp) * 64 + c4];
        }
        ks[r * 65 + c4 + 0] = kv.x; ks[r * 65 + c4 + 1] = kv.y;
        ks[r * 65 + c4 + 2] = kv.z; ks[r * 65 + c4 + 3] = kv.w;
        *(float4*)&vs[r * 64 + c4] = vv;
    }
    if (tid < 64) {
        int r = tid >> 4, c4 = (tid & 15) << 2;
        *(float4*)&kc[r * 64 + c4] = *(const float4*)&Kb[(size_t)r * 64 + c4];
        *(float4*)&vc[r * 64 + c4] = *(const float4*)&Vb[(size_t)r * 64 + c4];
    }
    __syncthreads();

    for (int pr = tid; pr < 64 * CTX; pr += 256) {
        int qi = pr / CTX, j = pr % CTX;
        const float* qrow = &qs[qi * 64];
        const float* krow;
        bool valid = true;
        if (j < NUM_CLS) {
            krow = &kc[j * 64];
        } else {
            int wq = j - NUM_CLS;
            int pos = l0 + qi - WIN + wq;
            valid = (pos >= 0) && (pos < L_PAT);
            krow = &ks[(qi + wq) * 65];
        }
        float a = 0.f;
#pragma unroll
        for (int d = 0; d < 64; d++) a = fmaf(qrow[d], krow[d], a);
        sc[qi * 72 + j] = valid ? a * 0.125f : -1e30f;
    }
    __syncthreads();

    {
        int row = tid >> 2, sub = tid & 3;
        float* srow = &sc[row * 72];
        float m = -INFINITY;
        for (int j = sub; j < CTX; j += 4) m = fmaxf(m, srow[j]);
        m = fmaxf(m, __shfl_xor_sync(0xffffffffu, m, 1));
        m = fmaxf(m, __shfl_xor_sync(0xffffffffu, m, 2));
        float sum = 0.f;
        for (int j = sub; j < CTX; j += 4) {
            float p = __expf(srow[j] - m);
            srow[j] = p;
            sum += p;
        }
        sum += __shfl_xor_sync(0xffffffffu, sum, 1);
        sum += __shfl_xor_sync(0xffffffffu, sum, 2);
        float inv = 1.0f / sum;
        for (int j = sub; j < CTX; j += 4) srow[j] *= inv;
    }
    __syncthreads();

    for (int i = tid; i < 64 * 16; i += 256) {
        int qi = i >> 4, d4 = (i & 15) << 2;
        const float* prow = &sc[qi * 72];
        float4 a = make_float4(0.f, 0.f, 0.f, 0.f);
#pragma unroll
        for (int j = 0; j < NUM_CLS; j++) {
            float p = prow[j];
            float4 vv = *(float4*)&vc[j * 64 + d4];
            a.x = fmaf(p, vv.x, a.x); a.y = fmaf(p, vv.y, a.y);
            a.z = fmaf(p, vv.z, a.z); a.w = fmaf(p, vv.w, a.w);
        }
#pragma unroll
        for (int wq = 0; wq < WLEN; wq++) {
            float p = prow[NUM_CLS + wq];
            float4 vv = *(float4*)&vs[(qi + wq) * 64 + d4];
            a.x = fmaf(p, vv.x, a.x); a.y = fmaf(p, vv.y, a.y);
            a.z = fmaf(p, vv.z, a.z); a.w = fmaf(p, vv.w, a.w);
        }
        *(float4*)&g_attn[(size_t)(NUM_CLS + l0 + qi) * 512 + h * 64 + d4] = a;
    }
}

// ---------------------------------------------------------------------------
extern "C" void kernel_launch(void* const* d_in, const int* in_sizes, int n_in,
                              void* d_out, int out_size) {
    const float* x      = (const float*)d_in[0];
    const float* coords = (const float*)d_in[1];
    const float* w_qkv  = (const float*)d_in[2];
    const float* b_qkv  = (const float*)d_in[3];
    const float* w_out  = (const float*)d_in[4];
    const float* b_out  = (const float*)d_in[5];
    float* out = (float*)d_out;

    float* attn_ptr = nullptr;
    cudaGetSymbolAddress((void**)&attn_ptr, g_attn);
    __nv_bfloat16 *xh, *xl, *wqh, *wql, *woh, *wol, *ah, *al;
    cudaGetSymbolAddress((void**)&xh, g_xh);
    cudaGetSymbolAddress((void**)&xl, g_xl);
    cudaGetSymbolAddress((void**)&wqh, g_wqh);
    cudaGetSymbolAddress((void**)&wql, g_wql);
    cudaGetSymbolAddress((void**)&woh, g_woh);
    cudaGetSymbolAddress((void**)&wol, g_wol);
    cudaGetSymbolAddress((void**)&ah, g_ah);
    cudaGetSymbolAddress((void**)&al, g_al);

    cudaFuncSetAttribute(gemm_bf16x3<0>, cudaFuncAttributeMaxDynamicSharedMemorySize, GEMM_SMEM);
    cudaFuncSetAttribute(gemm_bf16x3<1>, cudaFuncAttributeMaxDynamicSharedMemorySize, GEMM_SMEM);
    cudaFuncSetAttribute(patch_attn_kernel, cudaFuncAttributeMaxDynamicSharedMemorySize, PATCH_SMEM);

    // 1. splits
    split_kernel<<<(S_TOT * GK / 4 + 255) / 256, 256>>>(x, xh, xl, S_TOT * GK / 4);
    split_kernel<<<(1536 * GK / 4 + 255) / 256, 256>>>(w_qkv, wqh, wql, 1536 * GK / 4);
    split_kernel<<<(512 * GK / 4 + 255) / 256, 256>>>(w_out, woh, wol, 512 * GK / 4);

    // 2. QKV GEMM -> g_qkv scatter
    {
        dim3 grid(1536 / 128, (S_TOT + 127) / 128);
        gemm_bf16x3<1><<<grid, 256, GEMM_SMEM>>>(xh, xl, wqh, wql, b_qkv, nullptr, S_TOT, 0);
    }
    // 3. RoPE
    rope_kernel<<<L_PAT, 256>>>(coords);
    // 4. CLS attention
    cls_attn_kernel<<<32, 256>>>();
    // 5. Patch attention
    {
        dim3 grid(L_PAT / 64, H_NUM);
        patch_attn_kernel<<<grid, 256, PATCH_SMEM>>>();
    }
    // 6. split attention output
    split_kernel<<<(S_TOT * GK / 4 + 255) / 256, 256>>>(attn_ptr, ah, al, S_TOT * GK / 4);
    // 7. out projection
    {
        dim3 grid(512 / 128, (S_TOT + 127) / 128);
        gemm_bf16x3<0><<<grid, 256, GEMM_SMEM>>>(ah, al, woh, wol, b_out, out, S_TOT, 512);
    }
}

// round 5
// speedup vs baseline: 1.8285x; 1.1495x over previous
#include <cuda_runtime.h>
#include <cuda_bf16.h>
#include <math.h>
#include <stdint.h>

#define S_TOT 8196
#define L_PAT 8192
#define H_NUM 8
#define HD 64
#define NUM_CLS 4
#define WIN 32
#define WLEN 65
#define CTX 69
#define GK 512

// scratch: qkv in [sel][h][s][hd] layout, attn in [s][h*64+d]
__device__ float g_qkv[3ull * H_NUM * S_TOT * HD];
__device__ float g_attn[(size_t)S_TOT * 512];

extern __shared__ char dynsm[];

__device__ __forceinline__ uint32_t smem_u32(const void* p) {
    uint32_t a;
    asm("{ .reg .u64 t; cvta.to.shared.u64 t, %1; cvt.u32.u64 %0, t; }" : "=r"(a) : "l"(p));
    return a;
}
__device__ __forceinline__ void ldm_x4(uint32_t* r, uint32_t addr) {
    asm volatile("ldmatrix.sync.aligned.m8n8.x4.shared.b16 {%0,%1,%2,%3}, [%4];"
                 : "=r"(r[0]), "=r"(r[1]), "=r"(r[2]), "=r"(r[3]) : "r"(addr));
}
__device__ __forceinline__ void mma16816(float* c, const uint32_t* a, uint32_t b0, uint32_t b1) {
    asm volatile("mma.sync.aligned.m16n8k16.row.col.f32.bf16.bf16.f32 "
                 "{%0,%1,%2,%3}, {%4,%5,%6,%7}, {%8,%9}, {%0,%1,%2,%3};"
                 : "+f"(c[0]), "+f"(c[1]), "+f"(c[2]), "+f"(c[3])
                 : "r"(a[0]), "r"(a[1]), "r"(a[2]), "r"(a[3]), "r"(b0), "r"(b1));
}
__device__ __forceinline__ uint32_t packhi2(float a, float b) {
    __nv_bfloat162 t(__float2bfloat16(a), __float2bfloat16(b));
    return *(uint32_t*)&t;
}

// ---------------------------------------------------------------------------
// fused-split bf16x3 mma.sync GEMM: C = A(fp32)*B(fp32)^T + bias
// 512 threads (16 warps 4x4), CTA tile 128x128, warp tile 32x32.
// k chunks of 64, double-buffered smem, on-the-fly fp32 -> bf16 hi/lo split.
// MODE 0: row-major C.  MODE 1: scatter into g_qkv.
// ---------------------------------------------------------------------------
#define SMS 72
#define TILE_E (128 * SMS)                 // bf16 elems per operand tile
#define STAGE_E (4 * TILE_E)
#define TILE_B (TILE_E * 2)
#define STAGE_B (STAGE_E * 2)
#define GEMM_SMEM (2 * STAGE_B)            // 147456 B

template<int MODE>
__launch_bounds__(512)
__global__ void gemm_f32x3(const float* __restrict__ A, const float* __restrict__ B,
                           const float* __restrict__ bias,
                           float* __restrict__ C, int M, int Ntot) {
    __nv_bfloat16* sm = (__nv_bfloat16*)dynsm;

    const int tid = threadIdx.x;
    const int wid = tid >> 5;
    const int lane = tid & 31;
    const int wm = (wid >> 2) * 32;
    const int wn = (wid & 3) * 32;
    const int bm = blockIdx.y * 128;
    const int bn = blockIdx.x * 128;

    float c[2][4][4];
#pragma unroll
    for (int i = 0; i < 2; i++)
#pragma unroll
        for (int j = 0; j < 4; j++)
#pragma unroll
            for (int r = 0; r < 4; r++) c[i][j][r] = 0.f;

    const uint32_t smb = smem_u32(sm);
    const int lrow = lane & 15;
    const int lcol = (lane >> 4) * 8;

    // per-thread load slots: 4 float4 of A, 4 of B per stage
    float4 pa[4], pb[4];
    int lr[4], lc[4];
#pragma unroll
    for (int it = 0; it < 4; it++) {
        int fv = tid + it * 512;
        lr[it] = fv >> 4;
        lc[it] = (fv & 15) * 4;
    }

    auto ldg_stage = [&](int ch) {
#pragma unroll
        for (int it = 0; it < 4; it++) {
            int gr = bm + lr[it];
            pa[it] = make_float4(0.f, 0.f, 0.f, 0.f);
            if (gr < M) pa[it] = *(const float4*)&A[(size_t)gr * GK + ch * 64 + lc[it]];
            pb[it] = *(const float4*)&B[(size_t)(bn + lr[it]) * GK + ch * 64 + lc[it]];
        }
    };
    auto sts_stage = [&](int st) {
        __nv_bfloat16* sAh = sm + st * STAGE_E;
        __nv_bfloat16* sAl = sAh + TILE_E;
        __nv_bfloat16* sBh = sAh + 2 * TILE_E;
        __nv_bfloat16* sBl = sAh + 3 * TILE_E;
#pragma unroll
        for (int it = 0; it < 4; it++) {
            int off = lr[it] * SMS + lc[it];
            float4 v = pa[it];
            float hx = __bfloat162float(__float2bfloat16(v.x));
            float hy = __bfloat162float(__float2bfloat16(v.y));
            float hz = __bfloat162float(__float2bfloat16(v.z));
            float hw = __bfloat162float(__float2bfloat16(v.w));
            ((uint32_t*)(sAh + off))[0] = packhi2(v.x, v.y);
            ((uint32_t*)(sAh + off))[1] = packhi2(v.z, v.w);
            ((uint32_t*)(sAl + off))[0] = packhi2(v.x - hx, v.y - hy);
            ((uint32_t*)(sAl + off))[1] = packhi2(v.z - hz, v.w - hw);
            v = pb[it];
            hx = __bfloat162float(__float2bfloat16(v.x));
            hy = __bfloat162float(__float2bfloat16(v.y));
            hz = __bfloat162float(__float2bfloat16(v.z));
            hw = __bfloat162float(__float2bfloat16(v.w));
            ((uint32_t*)(sBh + off))[0] = packhi2(v.x, v.y);
            ((uint32_t*)(sBh + off))[1] = packhi2(v.z, v.w);
            ((uint32_t*)(sBl + off))[0] = packhi2(v.x - hx, v.y - hy);
            ((uint32_t*)(sBl + off))[1] = packhi2(v.z - hz, v.w - hw);
        }
    };

    ldg_stage(0);
    sts_stage(0);
    __syncthreads();

    for (int ch = 0; ch < GK / 64; ch++) {
        int st = ch & 1;
        if (ch < GK / 64 - 1) ldg_stage(ch + 1);

        uint32_t a_h = smb + st * STAGE_B;
        uint32_t a_l = a_h + TILE_B;
        uint32_t b_h = a_h + 2 * TILE_B;
        uint32_t b_l = a_h + 3 * TILE_B;

#pragma unroll
        for (int kk = 0; kk < 4; kk++) {
            uint32_t afh[2][4], afl[2][4], bfh[2][4], bfl[2][4];
#pragma unroll
            for (int mt = 0; mt < 2; mt++) {
                uint32_t off = ((wm + mt * 16 + lrow) * SMS + kk * 16 + lcol) * 2;
                ldm_x4(afh[mt], a_h + off);
                ldm_x4(afl[mt], a_l + off);
            }
#pragma unroll
            for (int g = 0; g < 2; g++) {
                uint32_t off = ((wn + g * 16 + lrow) * SMS + kk * 16 + lcol) * 2;
                ldm_x4(bfh[g], b_h + off);
                ldm_x4(bfl[g], b_l + off);
            }
#pragma unroll
            for (int mt = 0; mt < 2; mt++) {
#pragma unroll
                for (int nt = 0; nt < 4; nt++) {
                    int g = nt >> 1, s = nt & 1;
                    mma16816(c[mt][nt], afh[mt], bfh[g][s], bfh[g][s + 2]);
                    mma16816(c[mt][nt], afh[mt], bfl[g][s], bfl[g][s + 2]);
                    mma16816(c[mt][nt], afl[mt], bfh[g][s], bfh[g][s + 2]);
                }
            }
        }
        if (ch < GK / 64 - 1) sts_stage(st ^ 1);
        __syncthreads();
    }

    const int gid = lane >> 2;
    const int tig = lane & 3;
#pragma unroll
    for (int mt = 0; mt < 2; mt++) {
#pragma unroll
        for (int nt = 0; nt < 4; nt++) {
            int n = bn + wn + nt * 8 + tig * 2;
            float bx = bias[n], by = bias[n + 1];
            int m0 = bm + wm + mt * 16 + gid;
#pragma unroll
            for (int half = 0; half < 2; half++) {
                int m = m0 + half * 8;
                if (m >= M) continue;
                float vx = c[mt][nt][half * 2 + 0] + bx;
                float vy = c[mt][nt][half * 2 + 1] + by;
                if (MODE == 0) {
                    *(float2*)&C[(size_t)m * Ntot + n] = make_float2(vx, vy);
                } else {
                    int sel = n >> 9, h = (n >> 6) & 7, d = n & 63;
                    *(float2*)&g_qkv[(((size_t)(sel * 8 + h) * S_TOT) + m) * 64 + d] =
                        make_float2(vx, vy);
                }
            }
        }
    }
}

// ---------------------------------------------------------------------------
// RoPE2D in-place on q_p and k_p
// ---------------------------------------------------------------------------
__global__ void rope_kernel(const float* __restrict__ coords) {
    int l = blockIdx.x;
    int tid = threadIdx.x;
    int h = tid >> 5;
    int p = tid & 31;
    float cx = coords[2 * l + 0];
    float cy = coords[2 * l + 1];
    int j = p & 15;
    float freq = __expf(-(float)j * (9.210340371976184f / 16.0f));
    float coord = ((p < 16) ? cx : cy) * 1e-5f;
    float ang = coord * freq;
    float s, c;
    __sincosf(ang, &s, &c);

    size_t base_q = (((size_t)(0 * 8 + h) * S_TOT) + NUM_CLS + l) * 64 + 2 * p;
    size_t base_k = (((size_t)(1 * 8 + h) * S_TOT) + NUM_CLS + l) * 64 + 2 * p;
    float2 q = *(float2*)&g_qkv[base_q];
    *(float2*)&g_qkv[base_q] = make_float2(q.x * c - q.y * s, q.y * c + q.x * s);
    float2 k = *(float2*)&g_qkv[base_k];
    *(float2*)&g_qkv[base_k] = make_float2(k.x * c - k.y * s, k.y * c + k.x * s);
}

// ---------------------------------------------------------------------------
// CLS attention
// ---------------------------------------------------------------------------
__launch_bounds__(256)
__global__ void cls_attn_kernel() {
    __shared__ float qs[64];
    __shared__ float sc[S_TOT];
    __shared__ float red[32];
    __shared__ float osum[8][64];

    int h = blockIdx.x >> 2;
    int ci = blockIdx.x & 3;
    int tid = threadIdx.x;
    int lane = tid & 31, w = tid >> 5;

    const float* Q = &g_qkv[(((size_t)(0 * 8 + h) * S_TOT) + ci) * 64];
    const float* Kb = &g_qkv[(size_t)(1 * 8 + h) * S_TOT * 64];
    const float* Vb = &g_qkv[(size_t)(2 * 8 + h) * S_TOT * 64];

    if (tid < 64) qs[tid] = Q[tid];
    __syncthreads();

    float lmax = -INFINITY;
    for (int s = tid; s < S_TOT; s += 256) {
        const float4* kr = (const float4*)(Kb + (size_t)s * 64);
        float a = 0.f;
#pragma unroll
        for (int i = 0; i < 16; i++) {
            float4 kv = kr[i];
            float4 qv = *(float4*)&qs[i * 4];
            a += kv.x * qv.x + kv.y * qv.y + kv.z * qv.z + kv.w * qv.w;
        }
        a *= 0.125f;
        sc[s] = a;
        lmax = fmaxf(lmax, a);
    }
#pragma unroll
    for (int o = 16; o > 0; o >>= 1) lmax = fmaxf(lmax, __shfl_xor_sync(0xffffffffu, lmax, o));
    if (lane == 0) red[w] = lmax;
    __syncthreads();
    float gmax = red[0];
#pragma unroll
    for (int i = 1; i < 8; i++) gmax = fmaxf(gmax, red[i]);
    __syncthreads();

    float lsum = 0.f;
    for (int s = tid; s < S_TOT; s += 256) {
        float p = __expf(sc[s] - gmax);
        sc[s] = p;
        lsum += p;
    }
#pragma unroll
    for (int o = 16; o > 0; o >>= 1) lsum += __shfl_xor_sync(0xffffffffu, lsum, o);
    if (lane == 0) red[w] = lsum;
    __syncthreads();
    float gsum = 0.f;
#pragma unroll
    for (int i = 0; i < 8; i++) gsum += red[i];
    float inv = 1.0f / gsum;

    float acc[64];
#pragma unroll
    for (int d = 0; d < 64; d++) acc[d] = 0.f;
    for (int s = tid; s < S_TOT; s += 256) {
        float p = sc[s] * inv;
        const float4* vr = (const float4*)(Vb + (size_t)s * 64);
#pragma unroll
        for (int i = 0; i < 16; i++) {
            float4 vv = vr[i];
            acc[i * 4 + 0] = fmaf(p, vv.x, acc[i * 4 + 0]);
            acc[i * 4 + 1] = fmaf(p, vv.y, acc[i * 4 + 1]);
            acc[i * 4 + 2] = fmaf(p, vv.z, acc[i * 4 + 2]);
            acc[i * 4 + 3] = fmaf(p, vv.w, acc[i * 4 + 3]);
        }
    }
#pragma unroll
    for (int d = 0; d < 64; d++) {
        float v = acc[d];
#pragma unroll
        for (int o = 16; o > 0; o >>= 1) v += __shfl_down_sync(0xffffffffu, v, o);
        if (lane == 0) osum[w][d] = v;
    }
    __syncthreads();
    if (tid < 64) {
        float v = 0.f;
#pragma unroll
        for (int i = 0; i < 8; i++) v += osum[i][tid];
        g_attn[(size_t)ci * 512 + h * 64 + tid] = v;
    }
}

// ---------------------------------------------------------------------------
// Patch attention, register-blocked: 256 threads.
// thread = (qg, jp, dc): qg=tid>>4 owns 4 queries, dc=tid&3 owns 16 dims,
// jp=(tid>>2)&3 owns every 4th key-row. q/v reuse in registers, shfl combine.
// ---------------------------------------------------------------------------
#define KSS 68
#define PATCH_SMEM ((128*KSS + 128*KSS + 256 + 256 + 64*72) * 4)

__launch_bounds__(256)
__global__ void patch_attn_kernel() {
    float* sm = (float*)dynsm;
    float* ks = sm;                    // 128 x 68
    float* vs = ks + 128 * KSS;        // 128 x 68
    float* kc = vs + 128 * KSS;        // 4 x 64
    float* vc = kc + 256;              // 4 x 64
    float* sc = vc + 256;              // 64 x 72

    int h = blockIdx.y;
    int l0 = blockIdx.x * 64;
    int tid = threadIdx.x;

    const float* Qb = &g_qkv[(size_t)(0 * 8 + h) * S_TOT * 64];
    const float* Kb = &g_qkv[(size_t)(1 * 8 + h) * S_TOT * 64];
    const float* Vb = &g_qkv[(size_t)(2 * 8 + h) * S_TOT * 64];

    // window k/v rows: kp = l0-32+r, r in [0,128)
    for (int i = tid; i < 128 * 16; i += 256) {
        int r = i >> 4, c4 = (i & 15) << 2;
        int kp = l0 - WIN + r;
        float4 kv = make_float4(0.f, 0.f, 0.f, 0.f);
        float4 vv = make_float4(0.f, 0.f, 0.f, 0.f);
        if (kp >= 0 && kp < L_PAT) {
            kv = *(const float4*)&Kb[(size_t)(NUM_CLS + kp) * 64 + c4];
            vv = *(const float4*)&Vb[(size_t)(NUM_CLS + kp) * 64 + c4];
        }
        *(float4*)&ks[r * KSS + c4] = kv;
        *(float4*)&vs[r * KSS + c4] = vv;
    }
    if (tid < 64) {
        int r = tid >> 4, c4 = (tid & 15) << 2;
        *(float4*)&kc[r * 64 + c4] = *(const float4*)&Kb[(size_t)r * 64 + c4];
        *(float4*)&vc[r * 64 + c4] = *(const float4*)&Vb[(size_t)r * 64 + c4];
    }

    const int qg = tid >> 4;
    const int jp = (tid >> 2) & 3;
    const int dc = tid & 3;
    const int qi0 = qg * 4;
    const int dof = dc * 16;

    // q into registers (straight from gmem)
    float qreg[4][16];
#pragma unroll
    for (int qq = 0; qq < 4; qq++)
#pragma unroll
        for (int i = 0; i < 4; i++)
            *(float4*)&qreg[qq][i * 4] =
                *(const float4*)&Qb[(size_t)(NUM_CLS + l0 + qi0 + qq) * 64 + dof + i * 4];
    __syncthreads();

    // ---- scores ----
    for (int ri = jp; ri < 72; ri += 4) {
        const float* kr;
        if (ri < 4) kr = &kc[ri * 64 + dof];
        else        kr = &ks[(qi0 + ri - 4) * KSS + dof];
        float kf[16];
#pragma unroll
        for (int i = 0; i < 4; i++) *(float4*)&kf[i * 4] = *(const float4*)&kr[i * 4];
        float acc[4] = {0.f, 0.f, 0.f, 0.f};
#pragma unroll
        for (int dd = 0; dd < 16; dd++) {
            float kv = kf[dd];
            acc[0] = fmaf(qreg[0][dd], kv, acc[0]);
            acc[1] = fmaf(qreg[1][dd], kv, acc[1]);
            acc[2] = fmaf(qreg[2][dd], kv, acc[2]);
            acc[3] = fmaf(qreg[3][dd], kv, acc[3]);
        }
#pragma unroll
        for (int o = 1; o <= 2; o <<= 1) {
            acc[0] += __shfl_xor_sync(0xffffffffu, acc[0], o);
            acc[1] += __shfl_xor_sync(0xffffffffu, acc[1], o);
            acc[2] += __shfl_xor_sync(0xffffffffu, acc[2], o);
            acc[3] += __shfl_xor_sync(0xffffffffu, acc[3], o);
        }
        if (dc == 0) {
            if (ri < 4) {
#pragma unroll
                for (int qq = 0; qq < 4; qq++)
                    sc[(qi0 + qq) * 72 + ri] = acc[qq] * 0.125f;
            } else {
                int rw = ri - 4;
                int pos = l0 + qi0 + rw - WIN;      // absolute key position
                bool okpos = (pos >= 0) && (pos < L_PAT);
#pragma unroll
                for (int qq = 0; qq < 4; qq++) {
                    int w = rw - qq;
                    if (w >= 0 && w <= 64)
                        sc[(qi0 + qq) * 72 + 4 + w] = okpos ? acc[qq] * 0.125f : -1e30f;
                }
            }
        }
    }
    __syncthreads();

    // ---- softmax (4 threads per row) ----
    {
        int row = tid >> 2, sub = tid & 3;
        float* srow = &sc[row * 72];
        float m = -INFINITY;
        for (int j = sub; j < CTX; j += 4) m = fmaxf(m, srow[j]);
        m = fmaxf(m, __shfl_xor_sync(0xffffffffu, m, 1));
        m = fmaxf(m, __shfl_xor_sync(0xffffffffu, m, 2));
        float sum = 0.f;
        for (int j = sub; j < CTX; j += 4) {
            float p = __expf(srow[j] - m);
            srow[j] = p;
            sum += p;
        }
        sum += __shfl_xor_sync(0xffffffffu, sum, 1);
        sum += __shfl_xor_sync(0xffffffffu, sum, 2);
        float inv = 1.0f / sum;
        for (int j = sub; j < CTX; j += 4) srow[j] *= inv;
    }
    __syncthreads();

    // ---- PV ----
    float oacc[4][16];
#pragma unroll
    for (int qq = 0; qq < 4; qq++)
#pragma unroll
        for (int dd = 0; dd < 16; dd++) oacc[qq][dd] = 0.f;

    for (int ri = jp; ri < 72; ri += 4) {
        const float* vr;
        float p[4];
        if (ri < 4) {
            vr = &vc[ri * 64 + dof];
#pragma unroll
            for (int qq = 0; qq < 4; qq++) p[qq] = sc[(qi0 + qq) * 72 + ri];
        } else {
            int rw = ri - 4;
            vr = &vs[(qi0 + rw) * KSS + dof];
#pragma unroll
            for (int qq = 0; qq < 4; qq++) {
                int w = rw - qq;
                p[qq] = (w >= 0 && w <= 64) ? sc[(qi0 + qq) * 72 + 4 + w] : 0.f;
            }
        }
        float vf[16];
#pragma unroll
        for (int i = 0; i < 4; i++) *(float4*)&vf[i * 4] = *(const float4*)&vr[i * 4];
#pragma unroll
        for (int dd = 0; dd < 16; dd++) {
            float vv = vf[dd];
            oacc[0][dd] = fmaf(p[0], vv, oacc[0][dd]);
            oacc[1][dd] = fmaf(p[1], vv, oacc[1][dd]);
            oacc[2][dd] = fmaf(p[2], vv, oacc[2][dd]);
            oacc[3][dd] = fmaf(p[3], vv, oacc[3][dd]);
        }
    }
    // reduce over jp (lanes differing in bits 2..3)
#pragma unroll
    for (int o = 4; o <= 8; o <<= 1)
#pragma unroll
        for (int qq = 0; qq < 4; qq++)
#pragma unroll
            for (int dd = 0; dd < 16; dd++)
                oacc[qq][dd] += __shfl_xor_sync(0xffffffffu, oacc[qq][dd], o);

    if (jp == 0) {
#pragma unroll
        for (int qq = 0; qq < 4; qq++)
#pragma unroll
            for (int i = 0; i < 4; i++)
                *(float4*)&g_attn[(size_t)(NUM_CLS + l0 + qi0 + qq) * 512 + h * 64 + dof + i * 4] =
                    *(float4*)&oacc[qq][i * 4];
    }
}

// ---------------------------------------------------------------------------
extern "C" void kernel_launch(void* const* d_in, const int* in_sizes, int n_in,
                              void* d_out, int out_size) {
    const float* x      = (const float*)d_in[0];
    const float* coords = (const float*)d_in[1];
    const float* w_qkv  = (const float*)d_in[2];
    const float* b_qkv  = (const float*)d_in[3];
    const float* w_out  = (const float*)d_in[4];
    const float* b_out  = (const float*)d_in[5];
    float* out = (float*)d_out;

    float* attn_ptr = nullptr;
    cudaGetSymbolAddress((void**)&attn_ptr, g_attn);

    cudaFuncSetAttribute(gemm_f32x3<0>, cudaFuncAttributeMaxDynamicSharedMemorySize, GEMM_SMEM);
    cudaFuncSetAttribute(gemm_f32x3<1>, cudaFuncAttributeMaxDynamicSharedMemorySize, GEMM_SMEM);
    cudaFuncSetAttribute(patch_attn_kernel, cudaFuncAttributeMaxDynamicSharedMemorySize, PATCH_SMEM);

    // 1. QKV GEMM (fused split) -> g_qkv scatter
    {
        dim3 grid(1536 / 128, (S_TOT + 127) / 128);
        gemm_f32x3<1><<<grid, 512, GEMM_SMEM>>>(x, w_qkv, b_qkv, nullptr, S_TOT, 0);
    }
    // 2. RoPE
    rope_kernel<<<L_PAT, 256>>>(coords);
    // 3. CLS attention
    cls_attn_kernel<<<32, 256>>>();
    // 4. Patch attention
    {
        dim3 grid(L_PAT / 64, H_NUM);
        patch_attn_kernel<<<grid, 256, PATCH_SMEM>>>();
    }
    // 5. out projection (fused split)
    {
        dim3 grid(512 / 128, (S_TOT + 127) / 128);
        gemm_f32x3<0><<<grid, 512, GEMM_SMEM>>>(attn_ptr, w_out, b_out, out, S_TOT, 512);
    }
}

// round 6
// speedup vs baseline: 2.4389x; 1.3338x over previous
#include <cuda_runtime.h>
#include <cuda_bf16.h>
#include <math.h>
#include <stdint.h>

#define S_TOT 8196
#define L_PAT 8192
#define H_NUM 8
#define HD 64
#define NUM_CLS 4
#define WIN 32
#define WLEN 65
#define CTX 69
#define GK 512

// scratch: qkv in [sel][h][s][hd] layout, attn in [s][h*64+d]
__device__ float g_qkv[3ull * H_NUM * S_TOT * HD];
__device__ float g_attn[(size_t)S_TOT * 512];
__device__ float g_clsp[32 * 8 * 66];        // cls partials: [h*4+ci][chunk][m,sum,acc64]

__constant__ float c_ftbl[16] = {
    1.0f, 0.5623413252f, 0.3162277660f, 0.1778279410f,
    0.1f, 0.05623413252f, 0.03162277660f, 0.01778279410f,
    0.01f, 0.005623413252f, 0.003162277660f, 0.001778279410f,
    0.001f, 0.0005623413252f, 0.0003162277660f, 0.0001778279410f
};

extern __shared__ char dynsm[];

__device__ __forceinline__ uint32_t smem_u32(const void* p) {
    uint32_t a;
    asm("{ .reg .u64 t; cvta.to.shared.u64 t, %1; cvt.u32.u64 %0, t; }" : "=r"(a) : "l"(p));
    return a;
}
__device__ __forceinline__ void ldm_x4(uint32_t* r, uint32_t addr) {
    asm volatile("ldmatrix.sync.aligned.m8n8.x4.shared.b16 {%0,%1,%2,%3}, [%4];"
                 : "=r"(r[0]), "=r"(r[1]), "=r"(r[2]), "=r"(r[3]) : "r"(addr));
}
__device__ __forceinline__ void mma16816(float* c, const uint32_t* a, uint32_t b0, uint32_t b1) {
    asm volatile("mma.sync.aligned.m16n8k16.row.col.f32.bf16.bf16.f32 "
                 "{%0,%1,%2,%3}, {%4,%5,%6,%7}, {%8,%9}, {%0,%1,%2,%3};"
                 : "+f"(c[0]), "+f"(c[1]), "+f"(c[2]), "+f"(c[3])
                 : "r"(a[0]), "r"(a[1]), "r"(a[2]), "r"(a[3]), "r"(b0), "r"(b1));
}
__device__ __forceinline__ uint32_t prmt7632(uint32_t a, uint32_t b) {
    uint32_t r;
    asm("prmt.b32 %0, %1, %2, 0x7632;" : "=r"(r) : "r"(a), "r"(b));
    return r;
}
// fast exp on FMA pipe (x <= 0 domain; ~2.4e-6 rel err)
__device__ __forceinline__ float fexp(float x) {
    x = fmaxf(x, -80.0f);
    float z = fmaf(x, 1.442695041f, 12582912.0f);
    float n = z - 12582912.0f;
    float f = fmaf(x, 1.442695041f, -n);
    float r = 1.3333558e-3f;
    r = fmaf(r, f, 9.6181291e-3f);
    r = fmaf(r, f, 5.5504109e-2f);
    r = fmaf(r, f, 2.4022651e-1f);
    r = fmaf(r, f, 6.9314718e-1f);
    r = fmaf(r, f, 1.0f);
    return r * __int_as_float(((int)n + 127) << 23);
}

// ---------------------------------------------------------------------------
// fused-split bf16x3 mma.sync GEMM (truncation split via PRMT)
// ---------------------------------------------------------------------------
#define SMS 72
#define TILE_E (128 * SMS)
#define STAGE_E (4 * TILE_E)
#define TILE_B (TILE_E * 2)
#define STAGE_B (STAGE_E * 2)
#define GEMM_SMEM (2 * STAGE_B)

template<int MODE>
__launch_bounds__(512)
__global__ void gemm_f32x3(const float* __restrict__ A, const float* __restrict__ B,
                           const float* __restrict__ bias,
                           float* __restrict__ C, int M, int Ntot) {
    __nv_bfloat16* sm = (__nv_bfloat16*)dynsm;

    const int tid = threadIdx.x;
    const int wid = tid >> 5;
    const int lane = tid & 31;
    const int wm = (wid >> 2) * 32;
    const int wn = (wid & 3) * 32;
    const int bm = blockIdx.y * 128;
    const int bn = blockIdx.x * 128;

    float c[2][4][4];
#pragma unroll
    for (int i = 0; i < 2; i++)
#pragma unroll
        for (int j = 0; j < 4; j++)
#pragma unroll
            for (int r = 0; r < 4; r++) c[i][j][r] = 0.f;

    const uint32_t smb = smem_u32(sm);
    const int lrow = lane & 15;
    const int lcol = (lane >> 4) * 8;

    float4 pa[4], pb[4];
    int lr[4], lc[4];
#pragma unroll
    for (int it = 0; it < 4; it++) {
        int fv = tid + it * 512;
        lr[it] = fv >> 4;
        lc[it] = (fv & 15) * 4;
    }

    auto ldg_stage = [&](int ch) {
#pragma unroll
        for (int it = 0; it < 4; it++) {
            int gr = bm + lr[it];
            pa[it] = make_float4(0.f, 0.f, 0.f, 0.f);
            if (gr < M) pa[it] = *(const float4*)&A[(size_t)gr * GK + ch * 64 + lc[it]];
            pb[it] = *(const float4*)&B[(size_t)(bn + lr[it]) * GK + ch * 64 + lc[it]];
        }
    };
    auto split4 = [&](float4 v, __nv_bfloat16* ph, __nv_bfloat16* pl, int off) {
        uint32_t bx = __float_as_uint(v.x), by = __float_as_uint(v.y);
        uint32_t bz = __float_as_uint(v.z), bw = __float_as_uint(v.w);
        ((uint32_t*)(ph + off))[0] = prmt7632(bx, by);
        ((uint32_t*)(ph + off))[1] = prmt7632(bz, bw);
        float lx = v.x - __uint_as_float(bx & 0xFFFF0000u);
        float ly = v.y - __uint_as_float(by & 0xFFFF0000u);
        float lz = v.z - __uint_as_float(bz & 0xFFFF0000u);
        float lw = v.w - __uint_as_float(bw & 0xFFFF0000u);
        ((uint32_t*)(pl + off))[0] = prmt7632(__float_as_uint(lx), __float_as_uint(ly));
        ((uint32_t*)(pl + off))[1] = prmt7632(__float_as_uint(lz), __float_as_uint(lw));
    };
    auto sts_stage = [&](int st) {
        __nv_bfloat16* sAh = sm + st * STAGE_E;
        __nv_bfloat16* sAl = sAh + TILE_E;
        __nv_bfloat16* sBh = sAh + 2 * TILE_E;
        __nv_bfloat16* sBl = sAh + 3 * TILE_E;
#pragma unroll
        for (int it = 0; it < 4; it++) {
            int off = lr[it] * SMS + lc[it];
            split4(pa[it], sAh, sAl, off);
            split4(pb[it], sBh, sBl, off);
        }
    };

    ldg_stage(0);
    sts_stage(0);
    __syncthreads();

    for (int ch = 0; ch < GK / 64; ch++) {
        int st = ch & 1;
        if (ch < GK / 64 - 1) ldg_stage(ch + 1);

        uint32_t a_h = smb + st * STAGE_B;
        uint32_t a_l = a_h + TILE_B;
        uint32_t b_h = a_h + 2 * TILE_B;
        uint32_t b_l = a_h + 3 * TILE_B;

#pragma unroll
        for (int kk = 0; kk < 4; kk++) {
            uint32_t afh[2][4], afl[2][4], bfh[2][4], bfl[2][4];
#pragma unroll
            for (int mt = 0; mt < 2; mt++) {
                uint32_t off = ((wm + mt * 16 + lrow) * SMS + kk * 16 + lcol) * 2;
                ldm_x4(afh[mt], a_h + off);
                ldm_x4(afl[mt], a_l + off);
            }
#pragma unroll
            for (int g = 0; g < 2; g++) {
                uint32_t off = ((wn + g * 16 + lrow) * SMS + kk * 16 + lcol) * 2;
                ldm_x4(bfh[g], b_h + off);
                ldm_x4(bfl[g], b_l + off);
            }
#pragma unroll
            for (int mt = 0; mt < 2; mt++) {
#pragma unroll
                for (int nt = 0; nt < 4; nt++) {
                    int g = nt >> 1, s = nt & 1;
                    mma16816(c[mt][nt], afh[mt], bfh[g][s], bfh[g][s + 2]);
                    mma16816(c[mt][nt], afh[mt], bfl[g][s], bfl[g][s + 2]);
                    mma16816(c[mt][nt], afl[mt], bfh[g][s], bfh[g][s + 2]);
                }
            }
        }
        if (ch < GK / 64 - 1) sts_stage(st ^ 1);
        __syncthreads();
    }

    const int gid = lane >> 2;
    const int tig = lane & 3;
#pragma unroll
    for (int mt = 0; mt < 2; mt++) {
#pragma unroll
        for (int nt = 0; nt < 4; nt++) {
            int n = bn + wn + nt * 8 + tig * 2;
            float bx = bias[n], by = bias[n + 1];
            int m0 = bm + wm + mt * 16 + gid;
#pragma unroll
            for (int half = 0; half < 2; half++) {
                int m = m0 + half * 8;
                if (m >= M) continue;
                float vx = c[mt][nt][half * 2 + 0] + bx;
                float vy = c[mt][nt][half * 2 + 1] + by;
                if (MODE == 0) {
                    *(float2*)&C[(size_t)m * Ntot + n] = make_float2(vx, vy);
                } else {
                    int sel = n >> 9, h = (n >> 6) & 7, d = n & 63;
                    *(float2*)&g_qkv[(((size_t)(sel * 8 + h) * S_TOT) + m) * 64 + d] =
                        make_float2(vx, vy);
                }
            }
        }
    }
}

// ---------------------------------------------------------------------------
// RoPE2D: block = 8 tokens, thread = (token, pair); loops over h.
// MUFU per thread: 1 sincos. freq from constant table.
// ---------------------------------------------------------------------------
__launch_bounds__(256)
__global__ void rope_kernel(const float* __restrict__ coords) {
    int tid = threadIdx.x;
    int t = tid >> 5, p = tid & 31;
    int l = blockIdx.x * 8 + t;
    float cx = coords[2 * l + 0];
    float cy = coords[2 * l + 1];
    float freq = c_ftbl[p & 15];
    float coord = ((p < 16) ? cx : cy) * 1e-5f;
    float s, c;
    __sincosf(coord * freq, &s, &c);

#pragma unroll
    for (int h = 0; h < 8; h++) {
        size_t bq = ((size_t)h * S_TOT + NUM_CLS + l) * 64 + 2 * p;
        size_t bk = ((size_t)(8 + h) * S_TOT + NUM_CLS + l) * 64 + 2 * p;
        float2 q = *(float2*)&g_qkv[bq];
        *(float2*)&g_qkv[bq] = make_float2(q.x * c - q.y * s, q.y * c + q.x * s);
        float2 k = *(float2*)&g_qkv[bk];
        *(float2*)&g_qkv[bk] = make_float2(k.x * c - k.y * s, k.y * c + k.x * s);
    }
}

// ---------------------------------------------------------------------------
// CLS attention split-K: grid (32 hc, 8 chunks), 256 threads.
// Partial online softmax per chunk -> g_clsp. Combine kernel reduces.
// ---------------------------------------------------------------------------
#define CCHUNK 1025

__launch_bounds__(256)
__global__ void cls_part_kernel() {
    __shared__ float qs[64];
    __shared__ float sc[CCHUNK];
    __shared__ float red[8];
    __shared__ float osum[8][64];

    int hc = blockIdx.x;
    int h = hc >> 2, ci = hc & 3;
    int chunk = blockIdx.y;
    int k0 = chunk * CCHUNK;
    int k1 = min(S_TOT, k0 + CCHUNK);
    int nk = k1 - k0;
    int tid = threadIdx.x;
    int lane = tid & 31, w = tid >> 5;

    const float* Q = &g_qkv[(((size_t)h * S_TOT) + ci) * 64];
    const float* Kb = &g_qkv[(size_t)(8 + h) * S_TOT * 64];
    const float* Vb = &g_qkv[(size_t)(16 + h) * S_TOT * 64];

    if (tid < 64) qs[tid] = Q[tid];
    __syncthreads();

    float lmax = -INFINITY;
    for (int s = tid; s < nk; s += 256) {
        const float4* kr = (const float4*)(Kb + (size_t)(k0 + s) * 64);
        float a = 0.f;
#pragma unroll
        for (int i = 0; i < 16; i++) {
            float4 kv = kr[i];
            float4 qv = *(float4*)&qs[i * 4];
            a += kv.x * qv.x + kv.y * qv.y + kv.z * qv.z + kv.w * qv.w;
        }
        a *= 0.125f;
        sc[s] = a;
        lmax = fmaxf(lmax, a);
    }
#pragma unroll
    for (int o = 16; o > 0; o >>= 1) lmax = fmaxf(lmax, __shfl_xor_sync(0xffffffffu, lmax, o));
    if (lane == 0) red[w] = lmax;
    __syncthreads();
    float gmax = red[0];
#pragma unroll
    for (int i = 1; i < 8; i++) gmax = fmaxf(gmax, red[i]);
    __syncthreads();

    float lsum = 0.f;
    for (int s = tid; s < nk; s += 256) {
        float p = __expf(sc[s] - gmax);
        sc[s] = p;
        lsum += p;
    }
#pragma unroll
    for (int o = 16; o > 0; o >>= 1) lsum += __shfl_xor_sync(0xffffffffu, lsum, o);
    if (lane == 0) red[w] = lsum;
    __syncthreads();
    float gsum = 0.f;
#pragma unroll
    for (int i = 0; i < 8; i++) gsum += red[i];

    float acc[64];
#pragma unroll
    for (int d = 0; d < 64; d++) acc[d] = 0.f;
    for (int s = tid; s < nk; s += 256) {
        float p = sc[s];
        const float4* vr = (const float4*)(Vb + (size_t)(k0 + s) * 64);
#pragma unroll
        for (int i = 0; i < 16; i++) {
            float4 vv = vr[i];
            acc[i * 4 + 0] = fmaf(p, vv.x, acc[i * 4 + 0]);
            acc[i * 4 + 1] = fmaf(p, vv.y, acc[i * 4 + 1]);
            acc[i * 4 + 2] = fmaf(p, vv.z, acc[i * 4 + 2]);
            acc[i * 4 + 3] = fmaf(p, vv.w, acc[i * 4 + 3]);
        }
    }
#pragma unroll
    for (int d = 0; d < 64; d++) {
        float v = acc[d];
#pragma unroll
        for (int o = 16; o > 0; o >>= 1) v += __shfl_down_sync(0xffffffffu, v, o);
        if (lane == 0) osum[w][d] = v;
    }
    __syncthreads();

    float* dst = &g_clsp[((size_t)hc * 8 + chunk) * 66];
    if (tid == 0) { dst[0] = gmax; dst[1] = gsum; }
    if (tid < 64) {
        float v = 0.f;
#pragma unroll
        for (int i = 0; i < 8; i++) v += osum[i][tid];
        dst[2 + tid] = v;
    }
}

__global__ void cls_combine_kernel() {    // grid 32, 64 threads
    int hc = blockIdx.x;
    int h = hc >> 2, ci = hc & 3;
    int d = threadIdx.x;
    const float* base = &g_clsp[(size_t)hc * 8 * 66];
    float M = -INFINITY;
#pragma unroll
    for (int c = 0; c < 8; c++) M = fmaxf(M, base[c * 66]);
    float S = 0.f, A = 0.f;
#pragma unroll
    for (int c = 0; c < 8; c++) {
        float w = __expf(base[c * 66] - M);
        S = fmaf(base[c * 66 + 1], w, S);
        A = fmaf(base[c * 66 + 2 + d], w, A);
    }
    g_attn[(size_t)ci * 512 + h * 64 + d] = A / S;
}

// ---------------------------------------------------------------------------
// Patch attention (register-blocked, FMA-pipe exp)
// ---------------------------------------------------------------------------
#define KSS 68
#define PATCH_SMEM ((128*KSS + 128*KSS + 256 + 256 + 64*72) * 4)

__launch_bounds__(256)
__global__ void patch_attn_kernel() {
    float* sm = (float*)dynsm;
    float* ks = sm;
    float* vs = ks + 128 * KSS;
    float* kc = vs + 128 * KSS;
    float* vc = kc + 256;
    float* sc = vc + 256;

    int h = blockIdx.y;
    int l0 = blockIdx.x * 64;
    int tid = threadIdx.x;

    const float* Qb = &g_qkv[(size_t)h * S_TOT * 64];
    const float* Kb = &g_qkv[(size_t)(8 + h) * S_TOT * 64];
    const float* Vb = &g_qkv[(size_t)(16 + h) * S_TOT * 64];

    for (int i = tid; i < 128 * 16; i += 256) {
        int r = i >> 4, c4 = (i & 15) << 2;
        int kp = l0 - WIN + r;
        float4 kv = make_float4(0.f, 0.f, 0.f, 0.f);
        float4 vv = make_float4(0.f, 0.f, 0.f, 0.f);
        if (kp >= 0 && kp < L_PAT) {
            kv = *(const float4*)&Kb[(size_t)(NUM_CLS + kp) * 64 + c4];
            vv = *(const float4*)&Vb[(size_t)(NUM_CLS + kp) * 64 + c4];
        }
        *(float4*)&ks[r * KSS + c4] = kv;
        *(float4*)&vs[r * KSS + c4] = vv;
    }
    if (tid < 64) {
        int r = tid >> 4, c4 = (tid & 15) << 2;
        *(float4*)&kc[r * 64 + c4] = *(const float4*)&Kb[(size_t)r * 64 + c4];
        *(float4*)&vc[r * 64 + c4] = *(const float4*)&Vb[(size_t)r * 64 + c4];
    }

    const int qg = tid >> 4;
    const int jp = (tid >> 2) & 3;
    const int dc = tid & 3;
    const int qi0 = qg * 4;
    const int dof = dc * 16;

    float qreg[4][16];
#pragma unroll
    for (int qq = 0; qq < 4; qq++)
#pragma unroll
        for (int i = 0; i < 4; i++)
            *(float4*)&qreg[qq][i * 4] =
                *(const float4*)&Qb[(size_t)(NUM_CLS + l0 + qi0 + qq) * 64 + dof + i * 4];
    __syncthreads();

    for (int ri = jp; ri < 72; ri += 4) {
        const float* kr;
        if (ri < 4) kr = &kc[ri * 64 + dof];
        else        kr = &ks[(qi0 + ri - 4) * KSS + dof];
        float kf[16];
#pragma unroll
        for (int i = 0; i < 4; i++) *(float4*)&kf[i * 4] = *(const float4*)&kr[i * 4];
        float acc[4] = {0.f, 0.f, 0.f, 0.f};
#pragma unroll
        for (int dd = 0; dd < 16; dd++) {
            float kv = kf[dd];
            acc[0] = fmaf(qreg[0][dd], kv, acc[0]);
            acc[1] = fmaf(qreg[1][dd], kv, acc[1]);
            acc[2] = fmaf(qreg[2][dd], kv, acc[2]);
            acc[3] = fmaf(qreg[3][dd], kv, acc[3]);
        }
#pragma unroll
        for (int o = 1; o <= 2; o <<= 1) {
            acc[0] += __shfl_xor_sync(0xffffffffu, acc[0], o);
            acc[1] += __shfl_xor_sync(0xffffffffu, acc[1], o);
            acc[2] += __shfl_xor_sync(0xffffffffu, acc[2], o);
            acc[3] += __shfl_xor_sync(0xffffffffu, acc[3], o);
        }
        if (dc == 0) {
            if (ri < 4) {
#pragma unroll
                for (int qq = 0; qq < 4; qq++)
                    sc[(qi0 + qq) * 72 + ri] = acc[qq] * 0.125f;
            } else {
                int rw = ri - 4;
                int pos = l0 + qi0 + rw - WIN;
                bool okpos = (pos >= 0) && (pos < L_PAT);
#pragma unroll
                for (int qq = 0; qq < 4; qq++) {
                    int w = rw - qq;
                    if (w >= 0 && w <= 64)
                        sc[(qi0 + qq) * 72 + 4 + w] = okpos ? acc[qq] * 0.125f : -1e30f;
                }
            }
        }
    }
    __syncthreads();

    {
        int row = tid >> 2, sub = tid & 3;
        float* srow = &sc[row * 72];
        float m = -INFINITY;
        for (int j = sub; j < CTX; j += 4) m = fmaxf(m, srow[j]);
        m = fmaxf(m, __shfl_xor_sync(0xffffffffu, m, 1));
        m = fmaxf(m, __shfl_xor_sync(0xffffffffu, m, 2));
        float sum = 0.f;
        for (int j = sub; j < CTX; j += 4) {
            float p = fexp(srow[j] - m);
            srow[j] = p;
            sum += p;
        }
        sum += __shfl_xor_sync(0xffffffffu, sum, 1);
        sum += __shfl_xor_sync(0xffffffffu, sum, 2);
        float inv = 1.0f / sum;
        for (int j = sub; j < CTX; j += 4) srow[j] *= inv;
    }
    __syncthreads();

    float oacc[4][16];
#pragma unroll
    for (int qq = 0; qq < 4; qq++)
#pragma unroll
        for (int dd = 0; dd < 16; dd++) oacc[qq][dd] = 0.f;

    for (int ri = jp; ri < 72; ri += 4) {
        const float* vr;
        float p[4];
        if (ri < 4) {
            vr = &vc[ri * 64 + dof];
#pragma unroll
            for (int qq = 0; qq < 4; qq++) p[qq] = sc[(qi0 + qq) * 72 + ri];
        } else {
            int rw = ri - 4;
            vr = &vs[(qi0 + rw) * KSS + dof];
#pragma unroll
            for (int qq = 0; qq < 4; qq++) {
                int w = rw - qq;
                p[qq] = (w >= 0 && w <= 64) ? sc[(qi0 + qq) * 72 + 4 + w] : 0.f;
            }
        }
        float vf[16];
#pragma unroll
        for (int i = 0; i < 4; i++) *(float4*)&vf[i * 4] = *(const float4*)&vr[i * 4];
#pragma unroll
        for (int dd = 0; dd < 16; dd++) {
            float vv = vf[dd];
            oacc[0][dd] = fmaf(p[0], vv, oacc[0][dd]);
            oacc[1][dd] = fmaf(p[1], vv, oacc[1][dd]);
            oacc[2][dd] = fmaf(p[2], vv, oacc[2][dd]);
            oacc[3][dd] = fmaf(p[3], vv, oacc[3][dd]);
        }
    }
#pragma unroll
    for (int o = 4; o <= 8; o <<= 1)
#pragma unroll
        for (int qq = 0; qq < 4; qq++)
#pragma unroll
            for (int dd = 0; dd < 16; dd++)
                oacc[qq][dd] += __shfl_xor_sync(0xffffffffu, oacc[qq][dd], o);

    if (jp == 0) {
#pragma unroll
        for (int qq = 0; qq < 4; qq++)
#pragma unroll
            for (int i = 0; i < 4; i++)
                *(float4*)&g_attn[(size_t)(NUM_CLS + l0 + qi0 + qq) * 512 + h * 64 + dof + i * 4] =
                    *(float4*)&oacc[qq][i * 4];
    }
}

// ---------------------------------------------------------------------------
extern "C" void kernel_launch(void* const* d_in, const int* in_sizes, int n_in,
                              void* d_out, int out_size) {
    const float* x      = (const float*)d_in[0];
    const float* coords = (const float*)d_in[1];
    const float* w_qkv  = (const float*)d_in[2];
    const float* b_qkv  = (const float*)d_in[3];
    const float* w_out  = (const float*)d_in[4];
    const float* b_out  = (const float*)d_in[5];
    float* out = (float*)d_out;

    float* attn_ptr = nullptr;
    cudaGetSymbolAddress((void**)&attn_ptr, g_attn);

    cudaFuncSetAttribute(gemm_f32x3<0>, cudaFuncAttributeMaxDynamicSharedMemorySize, GEMM_SMEM);
    cudaFuncSetAttribute(gemm_f32x3<1>, cudaFuncAttributeMaxDynamicSharedMemorySize, GEMM_SMEM);
    cudaFuncSetAttribute(patch_attn_kernel, cudaFuncAttributeMaxDynamicSharedMemorySize, PATCH_SMEM);

    // 1. QKV GEMM (fused truncation split) -> g_qkv scatter
    {
        dim3 grid(1536 / 128, (S_TOT + 127) / 128);
        gemm_f32x3<1><<<grid, 512, GEMM_SMEM>>>(x, w_qkv, b_qkv, nullptr, S_TOT, 0);
    }
    // 2. RoPE (8 tokens per block)
    rope_kernel<<<L_PAT / 8, 256>>>(coords);
    // 3. CLS attention split-K + combine
    {
        dim3 grid(32, 8);
        cls_part_kernel<<<grid, 256>>>();
        cls_combine_kernel<<<32, 64>>>();
    }
    // 4. Patch attention
    {
        dim3 grid(L_PAT / 64, H_NUM);
        patch_attn_kernel<<<grid, 256, PATCH_SMEM>>>();
    }
    // 5. out projection (fused truncation split)
    {
        dim3 grid(512 / 128, (S_TOT + 127) / 128);
        gemm_f32x3<0><<<grid, 512, GEMM_SMEM>>>(attn_ptr, w_out, b_out, out, S_TOT, 512);
    }
}